// round 3
// baseline (speedup 1.0000x reference)
#include <cuda_runtime.h>
#include <math.h>

// Problem constants
#define BSZ   2
#define TSZ   16
#define NN    10000
#define INF   128
#define HIDD  256
#define OUTF  128
#define ESZ   160000
#define BT    (BSZ*TSZ)      // 32
#define BNR   (BSZ*NN)       // 20000
#define G3    (3*HIDD)       // 768

// ---------------- Scratch (static device globals; no allocation) -------------
__device__ float g_XA[(size_t)BT*NN*INF];    // agg(x):   [B*T, N, 128]
__device__ float g_AX[(size_t)BT*NN*G3];     // agg(x)@Wx+bx: [B*T, N, 768]
__device__ float g_H [(size_t)BNR*HIDD];     // hidden state [B*N, 256]
__device__ float g_HU[(size_t)BNR*HIDD];     // agg(h)
__device__ float g_G [(size_t)BNR*G3];       // agg(h)@Wh+bh
__device__ float g_WXC[INF*G3];
__device__ float g_WHC[HIDD*G3];
__device__ float g_BXC[G3];
__device__ float g_BHC[G3];
__device__ int   g_cnt[NN];
__device__ int   g_offs[NN+1];
__device__ int   g_cur[NN];
__device__ int   g_col[ESZ];
__device__ float g_wgt[ESZ];
__device__ float g_dinv[NN];

// ---------------- Graph preprocessing ----------------------------------------
__global__ void k_count(const int* __restrict__ ei) {
    int e = blockIdx.x*blockDim.x + threadIdx.x;
    if (e < ESZ) atomicAdd(&g_cnt[ei[ESZ + e]], 1);
}

__global__ void k_dinv() {
    int i = blockIdx.x*blockDim.x + threadIdx.x;
    if (i < NN) g_dinv[i] = rsqrtf((float)(g_cnt[i] + 1));  // +1 self loop
}

__global__ void k_scan() {
    __shared__ int part[1024];
    int tid = threadIdx.x;
    const int CH = (NN + 1023)/1024;      // 10
    int start = tid*CH;
    int s = 0;
    for (int i = 0; i < CH; i++) { int idx = start+i; if (idx < NN) s += g_cnt[idx]; }
    part[tid] = s;
    __syncthreads();
    for (int off = 1; off < 1024; off <<= 1) {
        int v = (tid >= off) ? part[tid-off] : 0;
        __syncthreads();
        part[tid] += v;
        __syncthreads();
    }
    int run = (tid > 0) ? part[tid-1] : 0;
    for (int i = 0; i < CH; i++) {
        int idx = start+i;
        if (idx < NN) { g_offs[idx] = run; run += g_cnt[idx]; }
    }
    if (tid == 0) g_offs[NN] = part[1023];
}

__global__ void k_fill(const int* __restrict__ ei) {
    int e = blockIdx.x*blockDim.x + threadIdx.x;
    if (e >= ESZ) return;
    int s = ei[e], d = ei[ESZ + e];
    int pos = g_offs[d] + atomicAdd(&g_cur[d], 1);
    g_col[pos] = s;
    g_wgt[pos] = g_dinv[s]*g_dinv[d];
}

// ---------------- Weight / bias concat ----------------------------------------
__global__ void k_concat(const float* __restrict__ wxr, const float* __restrict__ wxz,
                         const float* __restrict__ wxn,
                         const float* __restrict__ whr, const float* __restrict__ whz,
                         const float* __restrict__ whn,
                         const float* __restrict__ bxr, const float* __restrict__ bxz,
                         const float* __restrict__ bxn,
                         const float* __restrict__ bhr, const float* __restrict__ bhz,
                         const float* __restrict__ bhn) {
    int idx = blockIdx.x*blockDim.x + threadIdx.x;
    if (idx >= HIDD*G3) return;
    int k = idx / G3, c = idx % G3;
    int sel = c / HIDD, cc = c % HIDD;
    const float* wh = (sel == 0) ? whr : (sel == 1) ? whz : whn;
    g_WHC[idx] = wh[k*HIDD + cc];
    if (k < INF) {
        const float* wx = (sel == 0) ? wxr : (sel == 1) ? wxz : wxn;
        g_WXC[k*G3 + c] = wx[k*HIDD + cc];
    }
    if (k == 0) {
        g_BXC[c] = ((sel == 0) ? bxr : (sel == 1) ? bxz : bxn)[cc];
        g_BHC[c] = ((sel == 0) ? bhr : (sel == 1) ? bhz : bhn)[cc];
    }
}

// ---------------- Sparse aggregation (gather, CSR by dst) ---------------------
__global__ void k_aggx(const float* __restrict__ x) {
    int n = blockIdx.x, bt = blockIdx.y, c = threadIdx.x;
    size_t base = (size_t)bt*NN*INF;
    float d = g_dinv[n];
    float acc = d*d * x[base + (size_t)n*INF + c];
    int e1 = g_offs[n+1];
    for (int e = g_offs[n]; e < e1; e++)
        acc += g_wgt[e] * x[base + (size_t)g_col[e]*INF + c];
    g_XA[base + (size_t)n*INF + c] = acc;
}

__global__ void k_aggh() {
    int n = blockIdx.x, b = blockIdx.y, c = threadIdx.x;
    size_t base = (size_t)b*NN*HIDD;
    float d = g_dinv[n];
    float acc = d*d * g_H[base + (size_t)n*HIDD + c];
    int e1 = g_offs[n+1];
    for (int e = g_offs[n]; e < e1; e++)
        acc += g_wgt[e] * g_H[base + (size_t)g_col[e]*HIDD + c];
    g_HU[base + (size_t)n*HIDD + c] = acc;
}

// ---------------- SGEMM: C = A[MxK] * B[KxN] + bias, row-major -----------------
// BM=128, BN=128, BK=8, TM=TN=8, 256 threads.
// C rows can be re-mapped per batch: addr = C + (row/cbRows)*cbStride + (row%cbRows)*N
__global__ __launch_bounds__(256)
void k_sgemm(const float* __restrict__ A, const float* __restrict__ B,
             const float* __restrict__ bias, float* __restrict__ C,
             int M, int N, int K, int cbRows, long long cbStride) {
    const int BM = 128, BN = 128, BK = 8, TM = 8, TN = 8;
    __shared__ float As[BK][BM];
    __shared__ float Bs[BK][BN];
    int tid = threadIdx.x;
    int blockRow = blockIdx.y * BM;
    int blockCol = blockIdx.x * BN;
    int tx = tid % (BN/TN);      // 0..15
    int ty = tid / (BN/TN);      // 0..15

    float acc[TM][TN];
    #pragma unroll
    for (int i = 0; i < TM; i++)
        #pragma unroll
        for (int j = 0; j < TN; j++) acc[i][j] = 0.f;

    int aRow = tid / 2;          // 0..127
    int aCol = (tid % 2) * 4;    // 0 or 4
    int bRow = tid / 32;         // 0..7
    int bCol = (tid % 32) * 4;

    for (int k0 = 0; k0 < K; k0 += BK) {
        float4 av;
        int gRow = blockRow + aRow;
        if (gRow < M) av = *(const float4*)(A + (size_t)gRow*K + k0 + aCol);
        else          av = make_float4(0.f, 0.f, 0.f, 0.f);
        As[aCol+0][aRow] = av.x;
        As[aCol+1][aRow] = av.y;
        As[aCol+2][aRow] = av.z;
        As[aCol+3][aRow] = av.w;
        float4 bv = *(const float4*)(B + (size_t)(k0 + bRow)*N + blockCol + bCol);
        *(float4*)(&Bs[bRow][bCol]) = bv;
        __syncthreads();
        #pragma unroll
        for (int kk = 0; kk < BK; kk++) {
            float aReg[TM], bReg[TN];
            #pragma unroll
            for (int i = 0; i < TM; i++) aReg[i] = As[kk][ty*TM + i];
            #pragma unroll
            for (int j = 0; j < TN; j++) bReg[j] = Bs[kk][tx*TN + j];
            #pragma unroll
            for (int i = 0; i < TM; i++)
                #pragma unroll
                for (int j = 0; j < TN; j++)
                    acc[i][j] += aReg[i]*bReg[j];
        }
        __syncthreads();
    }

    // epilogue: bias + store (float4)
    int colBase = blockCol + tx*TN;
    float4 bias0 = *(const float4*)(bias + colBase);
    float4 bias1 = *(const float4*)(bias + colBase + 4);
    #pragma unroll
    for (int i = 0; i < TM; i++) {
        int row = blockRow + ty*TM + i;
        if (row >= M) continue;
        int rb = row / cbRows;
        int rr = row - rb*cbRows;
        float* crow = C + (size_t)rb*cbStride + (size_t)rr*N;
        float4 v0, v1;
        v0.x = acc[i][0] + bias0.x; v0.y = acc[i][1] + bias0.y;
        v0.z = acc[i][2] + bias0.z; v0.w = acc[i][3] + bias0.w;
        v1.x = acc[i][4] + bias1.x; v1.y = acc[i][5] + bias1.y;
        v1.z = acc[i][6] + bias1.z; v1.w = acc[i][7] + bias1.w;
        *(float4*)(crow + colBase)     = v0;
        *(float4*)(crow + colBase + 4) = v1;
    }
}

// ---------------- GRU pointwise update -----------------------------------------
__global__ void k_gru(int t) {
    int idx = blockIdx.x*blockDim.x + threadIdx.x;
    if (idx >= BNR*HIDD) return;
    int c  = idx % HIDD;
    int bn = idx / HIDD;            // b*NN + n
    int b  = bn / NN, n = bn % NN;
    size_t gi  = (size_t)bn*G3;
    size_t axi = ((size_t)(b*TSZ + t)*NN + n)*G3;
    float pr = g_AX[axi + c]        + g_G[gi + c];
    float pz = g_AX[axi + HIDD + c] + g_G[gi + HIDD + c];
    float r  = 1.f/(1.f + expf(-pr));
    float z  = 1.f/(1.f + expf(-pz));
    float nn = tanhf(g_AX[axi + 2*HIDD + c] + r * g_G[gi + 2*HIDD + c]);
    float h  = g_H[idx];
    g_H[idx] = (1.f - z)*h + z*nn;
}

// ---------------- Host launch ----------------------------------------------------
extern "C" void kernel_launch(void* const* d_in, const int* in_sizes, int n_in,
                              void* d_out, int out_size) {
    const float* x    = (const float*)d_in[0];
    const int*   ei   = (const int*)  d_in[1];
    const float* W_xr = (const float*)d_in[2];  const float* b_xr = (const float*)d_in[3];
    const float* W_hr = (const float*)d_in[4];  const float* b_hr = (const float*)d_in[5];
    const float* W_xz = (const float*)d_in[6];  const float* b_xz = (const float*)d_in[7];
    const float* W_hz = (const float*)d_in[8];  const float* b_hz = (const float*)d_in[9];
    const float* W_xn = (const float*)d_in[10]; const float* b_xn = (const float*)d_in[11];
    const float* W_hn = (const float*)d_in[12]; const float* b_hn = (const float*)d_in[13];
    const float* W_fc = (const float*)d_in[14]; const float* b_fc = (const float*)d_in[15];
    float* out = (float*)d_out;

    void *pXA, *pAX, *pH, *pHU, *pG, *pWXC, *pWHC, *pBXC, *pBHC, *pcnt, *pcur;
    cudaGetSymbolAddress(&pXA,  g_XA);
    cudaGetSymbolAddress(&pAX,  g_AX);
    cudaGetSymbolAddress(&pH,   g_H);
    cudaGetSymbolAddress(&pHU,  g_HU);
    cudaGetSymbolAddress(&pG,   g_G);
    cudaGetSymbolAddress(&pWXC, g_WXC);
    cudaGetSymbolAddress(&pWHC, g_WHC);
    cudaGetSymbolAddress(&pBXC, g_BXC);
    cudaGetSymbolAddress(&pBHC, g_BHC);
    cudaGetSymbolAddress(&pcnt, g_cnt);
    cudaGetSymbolAddress(&pcur, g_cur);

    // --- Graph preprocessing (deterministic up to fp-add order tolerance) ---
    cudaMemsetAsync(pcnt, 0, NN*sizeof(int), 0);
    k_count<<<(ESZ+255)/256, 256>>>(ei);
    k_dinv <<<(NN+255)/256, 256>>>();
    k_scan <<<1, 1024>>>();
    cudaMemsetAsync(pcur, 0, NN*sizeof(int), 0);
    k_fill <<<(ESZ+255)/256, 256>>>(ei);

    // --- Weight concat ---
    k_concat<<<(HIDD*G3+255)/256, 256>>>(W_xr, W_xz, W_xn, W_hr, W_hz, W_hn,
                                         b_xr, b_xz, b_xn, b_hr, b_hz, b_hn);

    // --- X path (hoisted out of the recurrence) ---
    k_aggx<<<dim3(NN, BT), INF>>>(x);
    {
        dim3 grid(G3/128, (BT*NN + 127)/128);   // 6 x 2500
        k_sgemm<<<grid, 256>>>((const float*)pXA, (const float*)pWXC,
                               (const float*)pBXC, (float*)pAX,
                               BT*NN, G3, INF, BT*NN, 0LL);
    }

    // --- Recurrence ---
    cudaMemsetAsync(pH, 0, (size_t)BNR*HIDD*sizeof(float), 0);
    for (int t = 0; t < TSZ; t++) {
        k_aggh<<<dim3(NN, BSZ), HIDD>>>();
        {
            dim3 grid(G3/128, (BNR + 127)/128);  // 6 x 157
            k_sgemm<<<grid, 256>>>((const float*)pHU, (const float*)pWHC,
                                   (const float*)pBHC, (float*)pG,
                                   BNR, G3, HIDD, BNR, 0LL);
        }
        k_gru<<<(BNR*HIDD + 255)/256, 256>>>(t);
        {
            dim3 grid(OUTF/128, (BNR + 127)/128); // 1 x 157
            k_sgemm<<<grid, 256>>>((const float*)pH, W_fc, b_fc,
                                   out + (size_t)t*NN*OUTF,
                                   BNR, OUTF, HIDD,
                                   NN, (long long)TSZ*NN*OUTF);
        }
    }
}

// round 4
// speedup vs baseline: 1.0033x; 1.0033x over previous
#include <cuda_runtime.h>
#include <math.h>

// Problem constants
#define BSZ   2
#define TSZ   16
#define NN    10000
#define INF   128
#define HIDD  256
#define OUTF  128
#define ESZ   160000
#define BT    (BSZ*TSZ)      // 32
#define BNR   (BSZ*NN)       // 20000
#define G3    (3*HIDD)       // 768

// ---------------- Scratch (static device globals; no allocation) -------------
__device__ float g_XA[(size_t)BT*NN*INF];    // agg(x):   [B*T, N, 128]
__device__ float g_AX[(size_t)BT*NN*G3];     // agg(x)@Wx+bx: [B*T, N, 768]
__device__ float g_H [(size_t)BNR*HIDD];     // hidden state [B*N, 256]
__device__ float g_HU[(size_t)BNR*HIDD];     // agg(h)
__device__ float g_G [(size_t)BNR*G3];       // agg(h)@Wh+bh
__device__ float g_WXC[INF*G3];
__device__ float g_WHC[HIDD*G3];
__device__ float g_BXC[G3];
__device__ float g_BHC[G3];
__device__ int   g_cnt[NN];
__device__ int   g_offs[NN+1];
__device__ int   g_cur[NN];
__device__ int   g_col[ESZ];
__device__ float g_wgt[ESZ];
__device__ float g_dinv[NN];

// ---------------- Graph preprocessing ----------------------------------------
__global__ void k_count(const int* __restrict__ ei) {
    int e = blockIdx.x*blockDim.x + threadIdx.x;
    if (e < ESZ) atomicAdd(&g_cnt[ei[ESZ + e]], 1);
}

__global__ void k_dinv() {
    int i = blockIdx.x*blockDim.x + threadIdx.x;
    if (i < NN) g_dinv[i] = rsqrtf((float)(g_cnt[i] + 1));  // +1 self loop
}

__global__ void k_scan() {
    __shared__ int part[1024];
    int tid = threadIdx.x;
    const int CH = (NN + 1023)/1024;      // 10
    int start = tid*CH;
    int s = 0;
    for (int i = 0; i < CH; i++) { int idx = start+i; if (idx < NN) s += g_cnt[idx]; }
    part[tid] = s;
    __syncthreads();
    for (int off = 1; off < 1024; off <<= 1) {
        int v = (tid >= off) ? part[tid-off] : 0;
        __syncthreads();
        part[tid] += v;
        __syncthreads();
    }
    int run = (tid > 0) ? part[tid-1] : 0;
    for (int i = 0; i < CH; i++) {
        int idx = start+i;
        if (idx < NN) { g_offs[idx] = run; run += g_cnt[idx]; }
    }
    if (tid == 0) g_offs[NN] = part[1023];
}

__global__ void k_fill(const int* __restrict__ ei) {
    int e = blockIdx.x*blockDim.x + threadIdx.x;
    if (e >= ESZ) return;
    int s = ei[e], d = ei[ESZ + e];
    int pos = g_offs[d] + atomicAdd(&g_cur[d], 1);
    g_col[pos] = s;
    g_wgt[pos] = g_dinv[s]*g_dinv[d];
}

// ---------------- Weight / bias concat ----------------------------------------
__global__ void k_concat(const float* __restrict__ wxr, const float* __restrict__ wxz,
                         const float* __restrict__ wxn,
                         const float* __restrict__ whr, const float* __restrict__ whz,
                         const float* __restrict__ whn,
                         const float* __restrict__ bxr, const float* __restrict__ bxz,
                         const float* __restrict__ bxn,
                         const float* __restrict__ bhr, const float* __restrict__ bhz,
                         const float* __restrict__ bhn) {
    int idx = blockIdx.x*blockDim.x + threadIdx.x;
    if (idx >= HIDD*G3) return;
    int k = idx / G3, c = idx % G3;
    int sel = c / HIDD, cc = c % HIDD;
    const float* wh = (sel == 0) ? whr : (sel == 1) ? whz : whn;
    g_WHC[idx] = wh[k*HIDD + cc];
    if (k < INF) {
        const float* wx = (sel == 0) ? wxr : (sel == 1) ? wxz : wxn;
        g_WXC[k*G3 + c] = wx[k*HIDD + cc];
    }
    if (k == 0) {
        g_BXC[c] = ((sel == 0) ? bxr : (sel == 1) ? bxz : bxn)[cc];
        g_BHC[c] = ((sel == 0) ? bhr : (sel == 1) ? bhz : bhn)[cc];
    }
}

// ---------------- Sparse aggregation (gather, CSR by dst) ---------------------
__global__ void k_aggx(const float* __restrict__ x) {
    int n = blockIdx.x, bt = blockIdx.y, c = threadIdx.x;
    size_t base = (size_t)bt*NN*INF;
    float d = g_dinv[n];
    float acc = d*d * x[base + (size_t)n*INF + c];
    int e1 = g_offs[n+1];
    for (int e = g_offs[n]; e < e1; e++)
        acc += g_wgt[e] * x[base + (size_t)g_col[e]*INF + c];
    g_XA[base + (size_t)n*INF + c] = acc;
}

__global__ void k_aggh() {
    int n = blockIdx.x, b = blockIdx.y, c = threadIdx.x;
    size_t base = (size_t)b*NN*HIDD;
    float d = g_dinv[n];
    float acc = d*d * g_H[base + (size_t)n*HIDD + c];
    int e1 = g_offs[n+1];
    for (int e = g_offs[n]; e < e1; e++)
        acc += g_wgt[e] * g_H[base + (size_t)g_col[e]*HIDD + c];
    g_HU[base + (size_t)n*HIDD + c] = acc;
}

// ---------------- SGEMM: C = A[MxK] * B[KxN] + bias, row-major -----------------
// BM=128, BN=128, BK=8, TM=TN=8, 256 threads.
// C rows can be re-mapped per batch: addr = C + (row/cbRows)*cbStride + (row%cbRows)*N
__global__ __launch_bounds__(256)
void k_sgemm(const float* __restrict__ A, const float* __restrict__ B,
             const float* __restrict__ bias, float* __restrict__ C,
             int M, int N, int K, int cbRows, long long cbStride) {
    const int BM = 128, BN = 128, BK = 8, TM = 8, TN = 8;
    __shared__ float As[BK][BM];
    __shared__ float Bs[BK][BN];
    int tid = threadIdx.x;
    int blockRow = blockIdx.y * BM;
    int blockCol = blockIdx.x * BN;
    int tx = tid % (BN/TN);      // 0..15
    int ty = tid / (BN/TN);      // 0..15

    float acc[TM][TN];
    #pragma unroll
    for (int i = 0; i < TM; i++)
        #pragma unroll
        for (int j = 0; j < TN; j++) acc[i][j] = 0.f;

    int aRow = tid / 2;          // 0..127
    int aCol = (tid % 2) * 4;    // 0 or 4
    int bRow = tid / 32;         // 0..7
    int bCol = (tid % 32) * 4;

    for (int k0 = 0; k0 < K; k0 += BK) {
        float4 av;
        int gRow = blockRow + aRow;
        if (gRow < M) av = *(const float4*)(A + (size_t)gRow*K + k0 + aCol);
        else          av = make_float4(0.f, 0.f, 0.f, 0.f);
        As[aCol+0][aRow] = av.x;
        As[aCol+1][aRow] = av.y;
        As[aCol+2][aRow] = av.z;
        As[aCol+3][aRow] = av.w;
        float4 bv = *(const float4*)(B + (size_t)(k0 + bRow)*N + blockCol + bCol);
        *(float4*)(&Bs[bRow][bCol]) = bv;
        __syncthreads();
        #pragma unroll
        for (int kk = 0; kk < BK; kk++) {
            float aReg[TM], bReg[TN];
            #pragma unroll
            for (int i = 0; i < TM; i++) aReg[i] = As[kk][ty*TM + i];
            #pragma unroll
            for (int j = 0; j < TN; j++) bReg[j] = Bs[kk][tx*TN + j];
            #pragma unroll
            for (int i = 0; i < TM; i++)
                #pragma unroll
                for (int j = 0; j < TN; j++)
                    acc[i][j] += aReg[i]*bReg[j];
        }
        __syncthreads();
    }

    // epilogue: bias + store (float4)
    int colBase = blockCol + tx*TN;
    float4 bias0 = *(const float4*)(bias + colBase);
    float4 bias1 = *(const float4*)(bias + colBase + 4);
    #pragma unroll
    for (int i = 0; i < TM; i++) {
        int row = blockRow + ty*TM + i;
        if (row >= M) continue;
        int rb = row / cbRows;
        int rr = row - rb*cbRows;
        float* crow = C + (size_t)rb*cbStride + (size_t)rr*N;
        float4 v0, v1;
        v0.x = acc[i][0] + bias0.x; v0.y = acc[i][1] + bias0.y;
        v0.z = acc[i][2] + bias0.z; v0.w = acc[i][3] + bias0.w;
        v1.x = acc[i][4] + bias1.x; v1.y = acc[i][5] + bias1.y;
        v1.z = acc[i][6] + bias1.z; v1.w = acc[i][7] + bias1.w;
        *(float4*)(crow + colBase)     = v0;
        *(float4*)(crow + colBase + 4) = v1;
    }
}

// ---------------- GRU pointwise update -----------------------------------------
__global__ void k_gru(int t) {
    int idx = blockIdx.x*blockDim.x + threadIdx.x;
    if (idx >= BNR*HIDD) return;
    int c  = idx % HIDD;
    int bn = idx / HIDD;            // b*NN + n
    int b  = bn / NN, n = bn % NN;
    size_t gi  = (size_t)bn*G3;
    size_t axi = ((size_t)(b*TSZ + t)*NN + n)*G3;
    float pr = g_AX[axi + c]        + g_G[gi + c];
    float pz = g_AX[axi + HIDD + c] + g_G[gi + HIDD + c];
    float r  = 1.f/(1.f + expf(-pr));
    float z  = 1.f/(1.f + expf(-pz));
    float nn = tanhf(g_AX[axi + 2*HIDD + c] + r * g_G[gi + 2*HIDD + c]);
    float h  = g_H[idx];
    g_H[idx] = (1.f - z)*h + z*nn;
}

// ---------------- Host launch ----------------------------------------------------
extern "C" void kernel_launch(void* const* d_in, const int* in_sizes, int n_in,
                              void* d_out, int out_size) {
    const float* x    = (const float*)d_in[0];
    const int*   ei   = (const int*)  d_in[1];
    const float* W_xr = (const float*)d_in[2];  const float* b_xr = (const float*)d_in[3];
    const float* W_hr = (const float*)d_in[4];  const float* b_hr = (const float*)d_in[5];
    const float* W_xz = (const float*)d_in[6];  const float* b_xz = (const float*)d_in[7];
    const float* W_hz = (const float*)d_in[8];  const float* b_hz = (const float*)d_in[9];
    const float* W_xn = (const float*)d_in[10]; const float* b_xn = (const float*)d_in[11];
    const float* W_hn = (const float*)d_in[12]; const float* b_hn = (const float*)d_in[13];
    const float* W_fc = (const float*)d_in[14]; const float* b_fc = (const float*)d_in[15];
    float* out = (float*)d_out;

    void *pXA, *pAX, *pH, *pHU, *pG, *pWXC, *pWHC, *pBXC, *pBHC, *pcnt, *pcur;
    cudaGetSymbolAddress(&pXA,  g_XA);
    cudaGetSymbolAddress(&pAX,  g_AX);
    cudaGetSymbolAddress(&pH,   g_H);
    cudaGetSymbolAddress(&pHU,  g_HU);
    cudaGetSymbolAddress(&pG,   g_G);
    cudaGetSymbolAddress(&pWXC, g_WXC);
    cudaGetSymbolAddress(&pWHC, g_WHC);
    cudaGetSymbolAddress(&pBXC, g_BXC);
    cudaGetSymbolAddress(&pBHC, g_BHC);
    cudaGetSymbolAddress(&pcnt, g_cnt);
    cudaGetSymbolAddress(&pcur, g_cur);

    // --- Graph preprocessing (deterministic up to fp-add order tolerance) ---
    cudaMemsetAsync(pcnt, 0, NN*sizeof(int), 0);
    k_count<<<(ESZ+255)/256, 256>>>(ei);
    k_dinv <<<(NN+255)/256, 256>>>();
    k_scan <<<1, 1024>>>();
    cudaMemsetAsync(pcur, 0, NN*sizeof(int), 0);
    k_fill <<<(ESZ+255)/256, 256>>>(ei);

    // --- Weight concat ---
    k_concat<<<(HIDD*G3+255)/256, 256>>>(W_xr, W_xz, W_xn, W_hr, W_hz, W_hn,
                                         b_xr, b_xz, b_xn, b_hr, b_hz, b_hn);

    // --- X path (hoisted out of the recurrence) ---
    k_aggx<<<dim3(NN, BT), INF>>>(x);
    {
        dim3 grid(G3/128, (BT*NN + 127)/128);   // 6 x 2500
        k_sgemm<<<grid, 256>>>((const float*)pXA, (const float*)pWXC,
                               (const float*)pBXC, (float*)pAX,
                               BT*NN, G3, INF, BT*NN, 0LL);
    }

    // --- Recurrence ---
    cudaMemsetAsync(pH, 0, (size_t)BNR*HIDD*sizeof(float), 0);
    for (int t = 0; t < TSZ; t++) {
        k_aggh<<<dim3(NN, BSZ), HIDD>>>();
        {
            dim3 grid(G3/128, (BNR + 127)/128);  // 6 x 157
            k_sgemm<<<grid, 256>>>((const float*)pHU, (const float*)pWHC,
                                   (const float*)pBHC, (float*)pG,
                                   BNR, G3, HIDD, BNR, 0LL);
        }
        k_gru<<<(BNR*HIDD + 255)/256, 256>>>(t);
        {
            dim3 grid(OUTF/128, (BNR + 127)/128); // 1 x 157
            k_sgemm<<<grid, 256>>>((const float*)pH, W_fc, b_fc,
                                   out + (size_t)t*NN*OUTF,
                                   BNR, OUTF, HIDD,
                                   NN, (long long)TSZ*NN*OUTF);
        }
    }
}